// round 2
// baseline (speedup 1.0000x reference)
#include <cuda_runtime.h>
#include <math.h>

#define CC 128
#define NNP 4096
#define BNT 16384          // B*N points
#define KNB 32
#define FFH 512

// ---------------- static device scratch (no allocation) ----------------
__device__ float g_dist[67108864];     // 4*4096*4096  (256MB)
__device__ int   g_idx[BNT * KNB];
__device__ float g_sq[BNT];
__device__ float g_q [BNT * CC];       // point-major (B*N, C)
__device__ float g_xk[BNT * CC];
__device__ float g_xv[BNT * CC];
__device__ float g_y1[BNT * CC];       // x + attn_out
__device__ float g_h [BNT * FFH];      // FFN hidden
__device__ float g_y2[BNT * CC];       // x1 + ff
__device__ float g_stats[512];         // [sum1|sq1|sum2|sq2] x 128
__device__ float g_sb1[256];           // scale,bias for BN1
__device__ float g_sb2[256];

// ---------------- K0: zero stats + squared norms ----------------
__global__ void k_prep(const float* __restrict__ x) {
    int i = blockIdx.x * blockDim.x + threadIdx.x;
    if (i < 512) g_stats[i] = 0.f;
    if (i >= BNT) return;
    int b = i >> 12, n = i & (NNP - 1);
    const float* xp = x + (size_t)b * CC * NNP + n;
    float s = 0.f;
#pragma unroll
    for (int c = 0; c < CC; c++) { float v = xp[(size_t)c * NNP]; s = fmaf(v, v, s); }
    g_sq[i] = s;
}

#define FMA16() do {                                                              \
    acc[0][0]=fmaf(a.x,bv.x,acc[0][0]); acc[0][1]=fmaf(a.x,bv.y,acc[0][1]);       \
    acc[0][2]=fmaf(a.x,bv.z,acc[0][2]); acc[0][3]=fmaf(a.x,bv.w,acc[0][3]);       \
    acc[1][0]=fmaf(a.y,bv.x,acc[1][0]); acc[1][1]=fmaf(a.y,bv.y,acc[1][1]);       \
    acc[1][2]=fmaf(a.y,bv.z,acc[1][2]); acc[1][3]=fmaf(a.y,bv.w,acc[1][3]);       \
    acc[2][0]=fmaf(a.z,bv.x,acc[2][0]); acc[2][1]=fmaf(a.z,bv.y,acc[2][1]);       \
    acc[2][2]=fmaf(a.z,bv.z,acc[2][2]); acc[2][3]=fmaf(a.z,bv.w,acc[2][3]);       \
    acc[3][0]=fmaf(a.w,bv.x,acc[3][0]); acc[3][1]=fmaf(a.w,bv.y,acc[3][1]);       \
    acc[3][2]=fmaf(a.w,bv.z,acc[3][2]); acc[3][3]=fmaf(a.w,bv.w,acc[3][3]);       \
} while(0)

// ---------------- K1: symmetric distance GEMM (fp32) ----------------
__global__ void __launch_bounds__(256) k_dist(const float* __restrict__ x) {
    int ti = blockIdx.x, tj = blockIdx.y, b = blockIdx.z;
    if (tj < ti) return;
    __shared__ __align__(16) float sm[2 * 4096 + 192];
    float* As = sm;
    float* Bs = sm + 4096;
    int t = threadIdx.x, tx = t & 15, ty = t >> 4;
    int i0 = ti * 64, j0 = tj * 64;
    const float* xb = x + (size_t)b * CC * NNP;
    float acc[4][4] = {};
    for (int k0 = 0; k0 < CC; k0 += 64) {
#pragma unroll
        for (int l = 0; l < 16; l++) {
            int idx = t + l * 256;
            int c = idx >> 6, p = idx & 63;
            As[idx] = xb[(size_t)(k0 + c) * NNP + i0 + p];
            Bs[idx] = xb[(size_t)(k0 + c) * NNP + j0 + p];
        }
        __syncthreads();
#pragma unroll 8
        for (int c = 0; c < 64; c++) {
            float4 a  = *(const float4*)&As[c * 64 + ty * 4];
            float4 bv = *(const float4*)&Bs[c * 64 + tx * 4];
            FMA16();
        }
        __syncthreads();
    }
    float sqi[4], sqj[4];
#pragma unroll
    for (int r = 0; r < 4; r++) sqi[r] = g_sq[(b << 12) + i0 + ty * 4 + r];
#pragma unroll
    for (int s = 0; s < 4; s++) sqj[s] = g_sq[(b << 12) + j0 + tx * 4 + s];
    size_t dbase = ((size_t)b << 24);
#pragma unroll
    for (int r = 0; r < 4; r++) {
        float4 o;
        o.x = sqi[r] + sqj[0] - 2.f * acc[r][0];
        o.y = sqi[r] + sqj[1] - 2.f * acc[r][1];
        o.z = sqi[r] + sqj[2] - 2.f * acc[r][2];
        o.w = sqi[r] + sqj[3] - 2.f * acc[r][3];
        *(float4*)&g_dist[dbase + (size_t)(i0 + ty * 4 + r) * NNP + j0 + tx * 4] = o;
    }
    if (ti != tj) {
        float* Ts = sm;   // 64 x 65 transpose buffer (reuses As/Bs)
#pragma unroll
        for (int r = 0; r < 4; r++)
#pragma unroll
            for (int s = 0; s < 4; s++)
                Ts[(tx * 4 + s) * 65 + ty * 4 + r] = sqi[r] + sqj[s] - 2.f * acc[r][s];
        __syncthreads();
#pragma unroll
        for (int l = 0; l < 16; l++) {
            int idx = t + l * 256;
            int jj = idx >> 6, ii = idx & 63;
            g_dist[dbase + (size_t)(j0 + jj) * NNP + i0 + ii] = Ts[jj * 65 + ii];
        }
    }
}

// ---------------- K2: per-row top-32 via histogram select ----------------
__device__ __forceinline__ int dbin(float v) {
    int b = (int)(v * 1.6f);
    return min(1023, max(0, b));
}

__global__ void __launch_bounds__(256) k_topk() {
    __shared__ float vals[NNP];
    __shared__ int hist[1024];
    __shared__ unsigned long long wred[8];
    __shared__ int sT, sC0, sCnt;
    int r = blockIdx.x, t = threadIdx.x;
    const float* src = g_dist + ((size_t)(r >> 12) << 24) + (size_t)(r & (NNP - 1)) * NNP;
#pragma unroll
    for (int l = 0; l < 4; l++) hist[t + l * 256] = 0;
    if (t == 0) sCnt = 0;
    __syncthreads();
#pragma unroll
    for (int l = 0; l < 16; l++) {
        float v = src[t + l * 256];
        vals[t + l * 256] = v;
        atomicAdd(&hist[dbin(v)], 1);
    }
    __syncthreads();
    if (t < 32) {
        int p = 0;
#pragma unroll
        for (int i = 0; i < 32; i++) p += hist[t * 32 + i];
        int cum = p;
#pragma unroll
        for (int off = 1; off < 32; off <<= 1) {
            int o = __shfl_up_sync(0xffffffffu, cum, off);
            if (t >= off) cum += o;
        }
        unsigned mask = __ballot_sync(0xffffffffu, cum >= KNB);
        int L = __ffs(mask) - 1;
        int cumBefore = __shfl_sync(0xffffffffu, cum - p, L);
        if (t == 0) {
            int c = cumBefore, T = L * 32;
            while (c + hist[T] < KNB) { c += hist[T]; T++; }
            sT = T; sC0 = c;
        }
    }
    __syncthreads();
    int T = sT, c0 = sC0;
#pragma unroll
    for (int l = 0; l < 16; l++) {
        int j = t + l * 256;
        if (dbin(vals[j]) < T) {
            int pos = atomicAdd(&sCnt, 1);
            g_idx[r * KNB + pos] = j;
        }
    }
    __syncthreads();
    int need = KNB - c0;
    for (int it = 0; it < need; it++) {
        unsigned long long best = ~0ULL;
#pragma unroll
        for (int l = 0; l < 16; l++) {
            int j = t + l * 256;
            float v = vals[j];
            if (dbin(v) == T) {
                unsigned u = __float_as_uint(v);
                u = (u & 0x80000000u) ? ~u : (u | 0x80000000u);
                unsigned long long key = ((unsigned long long)u << 32) | (unsigned)j;
                best = min(best, key);
            }
        }
#pragma unroll
        for (int off = 16; off; off >>= 1) {
            unsigned long long o = __shfl_xor_sync(0xffffffffu, best, off);
            best = min(best, o);
        }
        if ((t & 31) == 0) wred[t >> 5] = best;
        __syncthreads();
        if (t == 0) {
            unsigned long long bb = ~0ULL;
#pragma unroll
            for (int w = 0; w < 8; w++) bb = min(bb, wred[w]);
            int j = (int)(bb & 0xffffffffu);
            g_idx[r * KNB + c0 + it] = j;
            vals[j] = __int_as_float(0x7f800000);  // +inf, leaves bin T
        }
        __syncthreads();
    }
}

// ---------------- K3: fused qkv projection GEMM (M=384) ----------------
__global__ void __launch_bounds__(256) k_qkv(const float* __restrict__ x,
                                             const float* __restrict__ Wq,
                                             const float* __restrict__ Wk,
                                             const float* __restrict__ Wv) {
    __shared__ __align__(16) float Ws[32][68];
    __shared__ __align__(16) float Xs[32][68];
    int t = threadIdx.x, tx = t & 15, ty = t >> 4;
    int m0 = blockIdx.y * 64, p0 = blockIdx.x * 64;
    int b = p0 >> 12, n0 = p0 & (NNP - 1);
    const float* xb = x + (size_t)b * CC * NNP;
    float acc[4][4] = {};
    for (int k0 = 0; k0 < CC; k0 += 32) {
        {
            int c = t & 31, r0 = t >> 5;
            for (int rr = r0; rr < 64; rr += 8) {
                int m = m0 + rr;
                const float* Wsel = m < 128 ? Wq : (m < 256 ? Wk : Wv);
                Ws[c][rr] = Wsel[(m & 127) * CC + k0 + c];
            }
            int p = t & 63, cc = t >> 6;
            for (int c2 = cc; c2 < 32; c2 += 4)
                Xs[c2][p] = xb[(size_t)(k0 + c2) * NNP + n0 + p];
        }
        __syncthreads();
#pragma unroll
        for (int kk = 0; kk < 32; kk++) {
            float4 a  = *(const float4*)&Ws[kk][ty * 4];
            float4 bv = *(const float4*)&Xs[kk][tx * 4];
            FMA16();
        }
        __syncthreads();
    }
#pragma unroll
    for (int s = 0; s < 4; s++) {
        int pt = p0 + tx * 4 + s;
        int m = m0 + ty * 4;
        float4 v = make_float4(acc[0][s], acc[1][s], acc[2][s], acc[3][s]);
        float* dst = m < 128 ? &g_q[(size_t)pt * CC + m]
                   : (m < 256 ? &g_xk[(size_t)pt * CC + m - 128]
                              : &g_xv[(size_t)pt * CC + m - 256]);
        *(float4*)dst = v;
    }
}

// ---------------- K4: vector-sub attention + residual + BN1 stats ----------------
__global__ void __launch_bounds__(256) k_attn(const float* __restrict__ x) {
    __shared__ float ssum[128], ssq[128];
    int t = threadIdx.x, w = t >> 5, lane = t & 31;
    if (t < 128) { ssum[t] = 0.f; ssq[t] = 0.f; }
    __syncthreads();
    int base_unit = (blockIdx.x * 8 + w) * 8;
    for (int s = 0; s < 8; s++) {
        int u = base_unit + s;
        int i = u >> 2, h = u & 3;
        int c = h * 32 + lane;
        float q   = g_q [i * CC + c];
        float cki = g_xk[i * CC + c];
        float cvi = g_xv[i * CC + c];
        float acc = 0.f;
        const int* ip = g_idx + i * KNB;
        int bbase = i & ~(NNP - 1);
#pragma unroll 4
        for (int k = 0; k < KNB; k++) {
            int jg = bbase + ip[k];
            float kd = g_xk[jg * CC + c] - cki;
            float vd = g_xv[jg * CC + c] - cvi;
            float e = (q - kd) * 0.17677669529663689f;  // 1/sqrt(32)
            float m = e;
#pragma unroll
            for (int o = 16; o; o >>= 1) m = fmaxf(m, __shfl_xor_sync(0xffffffffu, m, o));
            float p = __expf(e - m);
            float sum = p;
#pragma unroll
            for (int o = 16; o; o >>= 1) sum += __shfl_xor_sync(0xffffffffu, sum, o);
            acc = fmaf(__fdividef(p, sum), vd, acc);
        }
        int b = i >> 12, n = i & (NNP - 1);
        float tv = x[((size_t)b * CC + c) * NNP + n] + acc;
        g_y1[i * CC + c] = tv;
        atomicAdd(&ssum[c], tv);
        atomicAdd(&ssq[c], tv * tv);
    }
    __syncthreads();
    if (t < 128) {
        atomicAdd(&g_stats[t], ssum[t]);
        atomicAdd(&g_stats[128 + t], ssq[t]);
    }
}

// ---------------- K5: BN finalize -> scale/bias ----------------
__global__ void k_bnfin(const float* __restrict__ g, const float* __restrict__ b, int which) {
    int c = threadIdx.x;
    int off = which ? 256 : 0;
    float* sb = which ? g_sb2 : g_sb1;
    float inv = 1.f / (float)BNT;
    float mean = g_stats[off + c] * inv;
    float var = g_stats[off + 128 + c] * inv - mean * mean;
    float sc = g[c] * rsqrtf(var + 1e-5f);
    sb[c] = sc;
    sb[128 + c] = b[c] - mean * sc;
}

// ---------------- K6: FFN1 (BN1-apply fused, LeakyReLU) ----------------
__global__ void __launch_bounds__(256) k_ffn1(const float* __restrict__ W1) {
    __shared__ __align__(16) float Ws[32][68];
    __shared__ __align__(16) float Xs[32][68];
    int t = threadIdx.x, tx = t & 15, ty = t >> 4;
    int m0 = blockIdx.y * 64, p0 = blockIdx.x * 64;
    float acc[4][4] = {};
    for (int k0 = 0; k0 < CC; k0 += 32) {
        {
            int c = t & 31, r0 = t >> 5;
            for (int rr = r0; rr < 64; rr += 8)
                Ws[c][rr] = W1[(m0 + rr) * CC + k0 + c];
            int c2 = t & 31, p1 = t >> 5;
            for (int p = p1; p < 64; p += 8)
                Xs[c2][p] = g_y1[(size_t)(p0 + p) * CC + k0 + c2] * g_sb1[k0 + c2] + g_sb1[128 + k0 + c2];
        }
        __syncthreads();
#pragma unroll
        for (int kk = 0; kk < 32; kk++) {
            float4 a  = *(const float4*)&Ws[kk][ty * 4];
            float4 bv = *(const float4*)&Xs[kk][tx * 4];
            FMA16();
        }
        __syncthreads();
    }
#pragma unroll
    for (int s = 0; s < 4; s++) {
        int pt = p0 + tx * 4 + s;
        int m = m0 + ty * 4;
        float4 v;
        v.x = acc[0][s] >= 0.f ? acc[0][s] : 0.2f * acc[0][s];
        v.y = acc[1][s] >= 0.f ? acc[1][s] : 0.2f * acc[1][s];
        v.z = acc[2][s] >= 0.f ? acc[2][s] : 0.2f * acc[2][s];
        v.w = acc[3][s] >= 0.f ? acc[3][s] : 0.2f * acc[3][s];
        *(float4*)&g_h[(size_t)pt * FFH + m] = v;
    }
}

// ---------------- K7: FFN2 + residual + BN2 stats ----------------
__global__ void __launch_bounds__(256) k_ffn2(const float* __restrict__ W2) {
    __shared__ __align__(16) float Ws[32][68];
    __shared__ __align__(16) float Xs[32][68];
    __shared__ float ssum[64], ssq[64];
    int t = threadIdx.x, tx = t & 15, ty = t >> 4;
    int m0 = blockIdx.y * 64, p0 = blockIdx.x * 64;
    if (t < 64) { ssum[t] = 0.f; ssq[t] = 0.f; }
    float acc[4][4] = {};
    for (int k0 = 0; k0 < FFH; k0 += 32) {
        {
            int c = t & 31, r0 = t >> 5;
            for (int rr = r0; rr < 64; rr += 8)
                Ws[c][rr] = W2[(m0 + rr) * FFH + k0 + c];
            int c2 = t & 31, p1 = t >> 5;
            for (int p = p1; p < 64; p += 8)
                Xs[c2][p] = g_h[(size_t)(p0 + p) * FFH + k0 + c2];
        }
        __syncthreads();
#pragma unroll
        for (int kk = 0; kk < 32; kk++) {
            float4 a  = *(const float4*)&Ws[kk][ty * 4];
            float4 bv = *(const float4*)&Xs[kk][tx * 4];
            FMA16();
        }
        __syncthreads();
    }
    float ls[4] = {0.f, 0.f, 0.f, 0.f}, lq[4] = {0.f, 0.f, 0.f, 0.f};
#pragma unroll
    for (int s = 0; s < 4; s++) {
        int pt = p0 + tx * 4 + s;
        int m = m0 + ty * 4;
        float4 y1v = *(const float4*)&g_y1[(size_t)pt * CC + m];
        float4 v;
        v.x = acc[0][s] + y1v.x * g_sb1[m + 0] + g_sb1[128 + m + 0];
        v.y = acc[1][s] + y1v.y * g_sb1[m + 1] + g_sb1[128 + m + 1];
        v.z = acc[2][s] + y1v.z * g_sb1[m + 2] + g_sb1[128 + m + 2];
        v.w = acc[3][s] + y1v.w * g_sb1[m + 3] + g_sb1[128 + m + 3];
        *(float4*)&g_y2[(size_t)pt * CC + m] = v;
        ls[0] += v.x; lq[0] += v.x * v.x;
        ls[1] += v.y; lq[1] += v.y * v.y;
        ls[2] += v.z; lq[2] += v.z * v.z;
        ls[3] += v.w; lq[3] += v.w * v.w;
    }
#pragma unroll
    for (int r = 0; r < 4; r++) {
        atomicAdd(&ssum[ty * 4 + r], ls[r]);
        atomicAdd(&ssq[ty * 4 + r], lq[r]);
    }
    __syncthreads();
    if (t < 64) {
        atomicAdd(&g_stats[256 + m0 + t], ssum[t]);
        atomicAdd(&g_stats[384 + m0 + t], ssq[t]);
    }
}

// ---------------- K8: BN2 apply + transpose to (B, C, N) ----------------
__global__ void __launch_bounds__(256) k_out(float* __restrict__ out) {
    __shared__ float tile[32][33];
    int b = blockIdx.z, c0 = blockIdx.y * 32, n0 = blockIdx.x * 32;
    int t = threadIdx.x, lx = t & 31, ly = t >> 5;
#pragma unroll
    for (int r = 0; r < 32; r += 8) {
        int n = n0 + ly + r;
        int pt = b * NNP + n;
        int c = c0 + lx;
        tile[ly + r][lx] = g_y2[(size_t)pt * CC + c] * g_sb2[c] + g_sb2[128 + c];
    }
    __syncthreads();
#pragma unroll
    for (int r = 0; r < 32; r += 8) {
        int c = c0 + ly + r;
        out[((size_t)b * CC + c) * NNP + n0 + lx] = tile[lx][ly + r];
    }
}

// ---------------- launch ----------------
extern "C" void kernel_launch(void* const* d_in, const int* in_sizes, int n_in,
                              void* d_out, int out_size) {
    const float* x  = (const float*)d_in[0];
    const float* Wq = (const float*)d_in[1];
    const float* Wk = (const float*)d_in[2];
    const float* Wv = (const float*)d_in[3];
    const float* W1 = (const float*)d_in[4];
    const float* W2 = (const float*)d_in[5];
    const float* g1 = (const float*)d_in[6];
    const float* b1 = (const float*)d_in[7];
    const float* g2 = (const float*)d_in[8];
    const float* b2 = (const float*)d_in[9];
    float* out = (float*)d_out;

    k_prep<<<64, 256>>>(x);
    k_qkv<<<dim3(256, 6), 256>>>(x, Wq, Wk, Wv);
    k_dist<<<dim3(64, 64, 4), 256>>>(x);
    k_topk<<<16384, 256>>>();
    k_attn<<<1024, 256>>>(x);
    k_bnfin<<<1, 128>>>(g1, b1, 0);
    k_ffn1<<<dim3(256, 8), 256>>>(W1);
    k_ffn2<<<dim3(256, 2), 256>>>(W2);
    k_bnfin<<<1, 128>>>(g2, b2, 1);
    k_out<<<dim3(128, 4, 4), 256>>>(out);
}

// round 4
// speedup vs baseline: 1.0556x; 1.0556x over previous
#include <cuda_runtime.h>
#include <math.h>

#define CC 128
#define NNP 4096
#define BNT 16384          // B*N points
#define KNB 32
#define FFH 512

#define TK_CAP 240.0f
#define TK_SCALE (1024.0f / TK_CAP)

// ---------------- static device scratch (no allocation) ----------------
__device__ float g_dist[67108864];     // 4*4096*4096  (256MB)
__device__ int   g_idx[BNT * KNB];
__device__ float g_sq[BNT];
__device__ float g_q [BNT * CC];       // point-major (B*N, C)
__device__ float g_xk[BNT * CC];
__device__ float g_xv[BNT * CC];
__device__ float g_y1[BNT * CC];       // x + attn_out
__device__ float g_h [BNT * FFH];      // FFN hidden
__device__ float g_y2[BNT * CC];       // x1 + ff
__device__ float g_stats[512];         // [sum1|sq1|sum2|sq2] x 128
__device__ float g_sb1[256];           // scale,bias for BN1
__device__ float g_sb2[256];

// ---------------- K0: zero stats + squared norms ----------------
__global__ void k_prep(const float* __restrict__ x) {
    int i = blockIdx.x * blockDim.x + threadIdx.x;
    if (i < 512) g_stats[i] = 0.f;
    if (i >= BNT) return;
    int b = i >> 12, n = i & (NNP - 1);
    const float* xp = x + (size_t)b * CC * NNP + n;
    float s = 0.f;
#pragma unroll
    for (int c = 0; c < CC; c++) { float v = xp[(size_t)c * NNP]; s = fmaf(v, v, s); }
    g_sq[i] = s;
}

#define FMA16() do {                                                              \
    acc[0][0]=fmaf(a.x,bv.x,acc[0][0]); acc[0][1]=fmaf(a.x,bv.y,acc[0][1]);       \
    acc[0][2]=fmaf(a.x,bv.z,acc[0][2]); acc[0][3]=fmaf(a.x,bv.w,acc[0][3]);       \
    acc[1][0]=fmaf(a.y,bv.x,acc[1][0]); acc[1][1]=fmaf(a.y,bv.y,acc[1][1]);       \
    acc[1][2]=fmaf(a.y,bv.z,acc[1][2]); acc[1][3]=fmaf(a.y,bv.w,acc[1][3]);       \
    acc[2][0]=fmaf(a.z,bv.x,acc[2][0]); acc[2][1]=fmaf(a.z,bv.y,acc[2][1]);       \
    acc[2][2]=fmaf(a.z,bv.z,acc[2][2]); acc[2][3]=fmaf(a.z,bv.w,acc[2][3]);       \
    acc[3][0]=fmaf(a.w,bv.x,acc[3][0]); acc[3][1]=fmaf(a.w,bv.y,acc[3][1]);       \
    acc[3][2]=fmaf(a.w,bv.z,acc[3][2]); acc[3][3]=fmaf(a.w,bv.w,acc[3][3]);       \
} while(0)

// ---------------- K1: symmetric distance GEMM (fp32) ----------------
__global__ void __launch_bounds__(256) k_dist(const float* __restrict__ x) {
    int ti = blockIdx.x, tj = blockIdx.y, b = blockIdx.z;
    if (tj < ti) return;
    __shared__ __align__(16) float sm[2 * 4096 + 192];
    float* As = sm;
    float* Bs = sm + 4096;
    int t = threadIdx.x, tx = t & 15, ty = t >> 4;
    int i0 = ti * 64, j0 = tj * 64;
    const float* xb = x + (size_t)b * CC * NNP;
    float acc[4][4] = {};
    for (int k0 = 0; k0 < CC; k0 += 64) {
#pragma unroll
        for (int l = 0; l < 16; l++) {
            int idx = t + l * 256;
            int c = idx >> 6, p = idx & 63;
            As[idx] = __ldg(&xb[(size_t)(k0 + c) * NNP + i0 + p]);
            Bs[idx] = __ldg(&xb[(size_t)(k0 + c) * NNP + j0 + p]);
        }
        __syncthreads();
#pragma unroll 8
        for (int c = 0; c < 64; c++) {
            float4 a  = *(const float4*)&As[c * 64 + ty * 4];
            float4 bv = *(const float4*)&Bs[c * 64 + tx * 4];
            FMA16();
        }
        __syncthreads();
    }
    float sqi[4], sqj[4];
#pragma unroll
    for (int r = 0; r < 4; r++) sqi[r] = g_sq[(b << 12) + i0 + ty * 4 + r];
#pragma unroll
    for (int s = 0; s < 4; s++) sqj[s] = g_sq[(b << 12) + j0 + tx * 4 + s];
    size_t dbase = ((size_t)b << 24);
#pragma unroll
    for (int r = 0; r < 4; r++) {
        float4 o;
        o.x = sqi[r] + sqj[0] - 2.f * acc[r][0];
        o.y = sqi[r] + sqj[1] - 2.f * acc[r][1];
        o.z = sqi[r] + sqj[2] - 2.f * acc[r][2];
        o.w = sqi[r] + sqj[3] - 2.f * acc[r][3];
        __stcs((float4*)&g_dist[dbase + (size_t)(i0 + ty * 4 + r) * NNP + j0 + tx * 4], o);
    }
    if (ti != tj) {
        float* Ts = sm;   // 64 x 65 transpose buffer (reuses As/Bs)
#pragma unroll
        for (int r = 0; r < 4; r++)
#pragma unroll
            for (int s = 0; s < 4; s++)
                Ts[(tx * 4 + s) * 65 + ty * 4 + r] = sqi[r] + sqj[s] - 2.f * acc[r][s];
        __syncthreads();
#pragma unroll
        for (int l = 0; l < 16; l++) {
            int idx = t + l * 256;
            int jj = idx >> 6, ii = idx & 63;
            __stcs(&g_dist[dbase + (size_t)(j0 + jj) * NNP + i0 + ii], Ts[jj * 65 + ii]);
        }
    }
}

// ---------------- K2: per-row top-32, cap-pruned histogram select ----------------
__device__ __forceinline__ int dbin(float v) {
    int b = (int)(v * TK_SCALE);
    return min(1023, max(0, b));
}

__global__ void __launch_bounds__(256) k_topk() {
    __shared__ __align__(16) float vals[NNP];        // 16 KB
    __shared__ int whist[4][1024];                   // 16 KB (per warp-pair)
    __shared__ int hist[1024];                       // 4 KB
    __shared__ unsigned long long wred[8];
    __shared__ int sT, sC0, sCnt;
    int r = blockIdx.x, t = threadIdx.x;
    int wp = (t >> 5) & 3;
    const float* src = g_dist + ((size_t)(r >> 12) << 24) + (size_t)(r & (NNP - 1)) * NNP;
#pragma unroll
    for (int l = 0; l < 16; l++) whist[0][t + l * 256] = 0;
    if (t == 0) sCnt = 0;
    __syncthreads();
    // load (streaming) + capped histogram
#pragma unroll
    for (int l = 0; l < 4; l++) {
        float4 v = __ldcs((const float4*)src + t + l * 256);
        ((float4*)vals)[t + l * 256] = v;
        if (v.x < TK_CAP) atomicAdd(&whist[wp][dbin(v.x)], 1);
        if (v.y < TK_CAP) atomicAdd(&whist[wp][dbin(v.y)], 1);
        if (v.z < TK_CAP) atomicAdd(&whist[wp][dbin(v.z)], 1);
        if (v.w < TK_CAP) atomicAdd(&whist[wp][dbin(v.w)], 1);
    }
    __syncthreads();
#pragma unroll
    for (int l = 0; l < 4; l++) {
        int bb = t + l * 256;
        hist[bb] = whist[0][bb] + whist[1][bb] + whist[2][bb] + whist[3][bb];
    }
    __syncthreads();
    // threshold bin search (warp 0)
    if (t < 32) {
        int p = 0;
#pragma unroll
        for (int i = 0; i < 32; i++) p += hist[t * 32 + i];
        int cum = p;
#pragma unroll
        for (int off = 1; off < 32; off <<= 1) {
            int o = __shfl_up_sync(0xffffffffu, cum, off);
            if (t >= off) cum += o;
        }
        int total = __shfl_sync(0xffffffffu, cum, 31);
        unsigned mask = __ballot_sync(0xffffffffu, cum >= KNB);
        int L = mask ? (__ffs(mask) - 1) : 0;
        int cumBefore = __shfl_sync(0xffffffffu, cum - p, L);
        if (t == 0) {
            if (total < KNB) { sT = -1; sC0 = 0; }      // fallback: exact select all
            else {
                int c = cumBefore, T = L * 32;
                while (c + hist[T] < KNB) { c += hist[T]; T++; }
                sT = T; sC0 = c;
            }
        }
    }
    __syncthreads();
    int T = sT, c0 = sC0;
    bool fb = (T < 0);
    if (!fb) {
#pragma unroll
        for (int l = 0; l < 16; l++) {
            int j = t + l * 256;
            float v = vals[j];
            if (v < TK_CAP && dbin(v) < T) {
                int pos = atomicAdd(&sCnt, 1);
                g_idx[r * KNB + pos] = j;
            }
        }
        __syncthreads();
    }
    int need = KNB - c0;
    for (int it = 0; it < need; it++) {
        unsigned long long best = ~0ULL;
#pragma unroll
        for (int l = 0; l < 16; l++) {
            int j = t + l * 256;
            float v = vals[j];
            if (fb || (v < TK_CAP && dbin(v) == T)) {
                unsigned u = __float_as_uint(v);
                u = (u & 0x80000000u) ? ~u : (u | 0x80000000u);
                unsigned long long key = ((unsigned long long)u << 32) | (unsigned)j;
                best = min(best, key);
            }
        }
#pragma unroll
        for (int off = 16; off; off >>= 1) {
            unsigned long long o = __shfl_xor_sync(0xffffffffu, best, off);
            best = min(best, o);
        }
        if ((t & 31) == 0) wred[t >> 5] = best;
        __syncthreads();
        if (t == 0) {
            unsigned long long bb = ~0ULL;
#pragma unroll
            for (int w = 0; w < 8; w++) bb = min(bb, wred[w]);
            int j = (int)(bb & 0xffffffffu);
            g_idx[r * KNB + c0 + it] = j;
            vals[j] = __int_as_float(0x7f800000);  // +inf: fails every predicate
        }
        __syncthreads();
    }
}

// ---------------- K3: fused qkv projection GEMM (M=384) ----------------
__global__ void __launch_bounds__(256) k_qkv(const float* __restrict__ x,
                                             const float* __restrict__ Wq,
                                             const float* __restrict__ Wk,
                                             const float* __restrict__ Wv) {
    __shared__ __align__(16) float Ws[32][68];
    __shared__ __align__(16) float Xs[32][68];
    int t = threadIdx.x, tx = t & 15, ty = t >> 4;
    int m0 = blockIdx.y * 64, p0 = blockIdx.x * 64;
    int b = p0 >> 12, n0 = p0 & (NNP - 1);
    const float* xb = x + (size_t)b * CC * NNP;
    float acc[4][4] = {};
    for (int k0 = 0; k0 < CC; k0 += 32) {
        {
            int c = t & 31, r0 = t >> 5;
            for (int rr = r0; rr < 64; rr += 8) {
                int m = m0 + rr;
                const float* Wsel = m < 128 ? Wq : (m < 256 ? Wk : Wv);
                Ws[c][rr] = Wsel[(m & 127) * CC + k0 + c];
            }
            int p = t & 63, cc = t >> 6;
            for (int c2 = cc; c2 < 32; c2 += 4)
                Xs[c2][p] = xb[(size_t)(k0 + c2) * NNP + n0 + p];
        }
        __syncthreads();
#pragma unroll
        for (int kk = 0; kk < 32; kk++) {
            float4 a  = *(const float4*)&Ws[kk][ty * 4];
            float4 bv = *(const float4*)&Xs[kk][tx * 4];
            FMA16();
        }
        __syncthreads();
    }
#pragma unroll
    for (int s = 0; s < 4; s++) {
        int pt = p0 + tx * 4 + s;
        int m = m0 + ty * 4;
        float4 v = make_float4(acc[0][s], acc[1][s], acc[2][s], acc[3][s]);
        float* dst = m < 128 ? &g_q[(size_t)pt * CC + m]
                   : (m < 256 ? &g_xk[(size_t)pt * CC + m - 128]
                              : &g_xv[(size_t)pt * CC + m - 256]);
        *(float4*)dst = v;
    }
}

// ---------------- K4: vector-sub attention (all heads per warp) + residual + BN1 stats ----------------
__global__ void __launch_bounds__(256) k_attn(const float* __restrict__ x) {
    __shared__ float ssum[128], ssq[128];
    int t = threadIdx.x, w = t >> 5, lane = t & 31;
    if (t < 128) { ssum[t] = 0.f; ssq[t] = 0.f; }
    __syncthreads();
    const float inv = 0.17677669529663689f;  // 1/sqrt(32)
    int c4 = lane * 4;
    float ls[4] = {0.f,0.f,0.f,0.f}, lq[4] = {0.f,0.f,0.f,0.f};
    for (int s = 0; s < 4; s++) {
        int i = (blockIdx.x * 8 + w) * 4 + s;
        float4 qv = *(const float4*)&g_q [(size_t)i * CC + c4];
        float4 ki = *(const float4*)&g_xk[(size_t)i * CC + c4];
        float4 vi = *(const float4*)&g_xv[(size_t)i * CC + c4];
        float4 qc;
        qc.x = (qv.x + ki.x) * inv; qc.y = (qv.y + ki.y) * inv;
        qc.z = (qv.z + ki.z) * inv; qc.w = (qv.w + ki.w) * inv;
        float4 a1 = {0.f,0.f,0.f,0.f}, a2 = {0.f,0.f,0.f,0.f};
        int bbase = i & ~(NNP - 1);
        int myidx = g_idx[i * KNB + lane];
#pragma unroll 4
        for (int k = 0; k < KNB; k++) {
            int jg = bbase + __shfl_sync(0xffffffffu, myidx, k);
            float4 k4 = *(const float4*)&g_xk[(size_t)jg * CC + c4];
            float4 v4 = *(const float4*)&g_xv[(size_t)jg * CC + c4];
            float px = __expf(fmaf(-inv, k4.x, qc.x));
            float py = __expf(fmaf(-inv, k4.y, qc.y));
            float pz = __expf(fmaf(-inv, k4.z, qc.z));
            float pw = __expf(fmaf(-inv, k4.w, qc.w));
            float sl = (px + py) + (pz + pw);
            sl += __shfl_xor_sync(0xffffffffu, sl, 1);
            sl += __shfl_xor_sync(0xffffffffu, sl, 2);
            sl += __shfl_xor_sync(0xffffffffu, sl, 4);   // softmax denom over D=32 (8-lane group)
            float rc = __fdividef(1.0f, sl);
            float wx = px * rc, wy = py * rc, wz = pz * rc, ww = pw * rc;
            a1.x = fmaf(wx, v4.x, a1.x); a1.y = fmaf(wy, v4.y, a1.y);
            a1.z = fmaf(wz, v4.z, a1.z); a1.w = fmaf(ww, v4.w, a1.w);
            a2.x += wx; a2.y += wy; a2.z += wz; a2.w += ww;
        }
        int b = i >> 12, n = i & (NNP - 1);
        const float* xb = &x[((size_t)b * CC + c4) * NNP + n];
        float4 o;
        o.x = xb[0 * (size_t)NNP] + a1.x - vi.x * a2.x;
        o.y = xb[1 * (size_t)NNP] + a1.y - vi.y * a2.y;
        o.z = xb[2 * (size_t)NNP] + a1.z - vi.z * a2.z;
        o.w = xb[3 * (size_t)NNP] + a1.w - vi.w * a2.w;
        *(float4*)&g_y1[(size_t)i * CC + c4] = o;
        ls[0] += o.x; lq[0] += o.x * o.x;
        ls[1] += o.y; lq[1] += o.y * o.y;
        ls[2] += o.z; lq[2] += o.z * o.z;
        ls[3] += o.w; lq[3] += o.w * o.w;
    }
#pragma unroll
    for (int r = 0; r < 4; r++) {
        atomicAdd(&ssum[c4 + r], ls[r]);
        atomicAdd(&ssq[c4 + r], lq[r]);
    }
    __syncthreads();
    if (t < 128) {
        atomicAdd(&g_stats[t], ssum[t]);
        atomicAdd(&g_stats[128 + t], ssq[t]);
    }
}

// ---------------- K5: BN finalize -> scale/bias ----------------
__global__ void k_bnfin(const float* __restrict__ g, const float* __restrict__ b, int which) {
    int c = threadIdx.x;
    int off = which ? 256 : 0;
    float* sb = which ? g_sb2 : g_sb1;
    float invn = 1.f / (float)BNT;
    float mean = g_stats[off + c] * invn;
    float var = g_stats[off + 128 + c] * invn - mean * mean;
    float sc = g[c] * rsqrtf(var + 1e-5f);
    sb[c] = sc;
    sb[128 + c] = b[c] - mean * sc;
}

// ---------------- K6: FFN1 (BN1-apply fused, LeakyReLU) ----------------
__global__ void __launch_bounds__(256) k_ffn1(const float* __restrict__ W1) {
    __shared__ __align__(16) float Ws[32][68];
    __shared__ __align__(16) float Xs[32][68];
    int t = threadIdx.x, tx = t & 15, ty = t >> 4;
    int m0 = blockIdx.y * 64, p0 = blockIdx.x * 64;
    float acc[4][4] = {};
    for (int k0 = 0; k0 < CC; k0 += 32) {
        {
            int c = t & 31, r0 = t >> 5;
            for (int rr = r0; rr < 64; rr += 8)
                Ws[c][rr] = W1[(m0 + rr) * CC + k0 + c];
            int c2 = t & 31, p1 = t >> 5;
            for (int p = p1; p < 64; p += 8)
                Xs[c2][p] = g_y1[(size_t)(p0 + p) * CC + k0 + c2] * g_sb1[k0 + c2] + g_sb1[128 + k0 + c2];
        }
        __syncthreads();
#pragma unroll
        for (int kk = 0; kk < 32; kk++) {
            float4 a  = *(const float4*)&Ws[kk][ty * 4];
            float4 bv = *(const float4*)&Xs[kk][tx * 4];
            FMA16();
        }
        __syncthreads();
    }
#pragma unroll
    for (int s = 0; s < 4; s++) {
        int pt = p0 + tx * 4 + s;
        int m = m0 + ty * 4;
        float4 v;
        v.x = acc[0][s] >= 0.f ? acc[0][s] : 0.2f * acc[0][s];
        v.y = acc[1][s] >= 0.f ? acc[1][s] : 0.2f * acc[1][s];
        v.z = acc[2][s] >= 0.f ? acc[2][s] : 0.2f * acc[2][s];
        v.w = acc[3][s] >= 0.f ? acc[3][s] : 0.2f * acc[3][s];
        *(float4*)&g_h[(size_t)pt * FFH + m] = v;
    }
}

// ---------------- K7: FFN2 + residual + BN2 stats ----------------
__global__ void __launch_bounds__(256) k_ffn2(const float* __restrict__ W2) {
    __shared__ __align__(16) float Ws[32][68];
    __shared__ __align__(16) float Xs[32][68];
    __shared__ float ssum[64], ssq[64];
    int t = threadIdx.x, tx = t & 15, ty = t >> 4;
    int m0 = blockIdx.y * 64, p0 = blockIdx.x * 64;
    if (t < 64) { ssum[t] = 0.f; ssq[t] = 0.f; }
    float acc[4][4] = {};
    for (int k0 = 0; k0 < FFH; k0 += 32) {
        {
            int c = t & 31, r0 = t >> 5;
            for (int rr = r0; rr < 64; rr += 8)
                Ws[c][rr] = W2[(m0 + rr) * FFH + k0 + c];
            int c2 = t & 31, p1 = t >> 5;
            for (int p = p1; p < 64; p += 8)
                Xs[c2][p] = g_h[(size_t)(p0 + p) * FFH + k0 + c2];
        }
        __syncthreads();
#pragma unroll
        for (int kk = 0; kk < 32; kk++) {
            float4 a  = *(const float4*)&Ws[kk][ty * 4];
            float4 bv = *(const float4*)&Xs[kk][tx * 4];
            FMA16();
        }
        __syncthreads();
    }
    float ls[4] = {0.f, 0.f, 0.f, 0.f}, lq[4] = {0.f, 0.f, 0.f, 0.f};
#pragma unroll
    for (int s = 0; s < 4; s++) {
        int pt = p0 + tx * 4 + s;
        int m = m0 + ty * 4;
        float4 y1v = *(const float4*)&g_y1[(size_t)pt * CC + m];
        float4 v;
        v.x = acc[0][s] + y1v.x * g_sb1[m + 0] + g_sb1[128 + m + 0];
        v.y = acc[1][s] + y1v.y * g_sb1[m + 1] + g_sb1[128 + m + 1];
        v.z = acc[2][s] + y1v.z * g_sb1[m + 2] + g_sb1[128 + m + 2];
        v.w = acc[3][s] + y1v.w * g_sb1[m + 3] + g_sb1[128 + m + 3];
        *(float4*)&g_y2[(size_t)pt * CC + m] = v;
        ls[0] += v.x; lq[0] += v.x * v.x;
        ls[1] += v.y; lq[1] += v.y * v.y;
        ls[2] += v.z; lq[2] += v.z * v.z;
        ls[3] += v.w; lq[3] += v.w * v.w;
    }
#pragma unroll
    for (int r = 0; r < 4; r++) {
        atomicAdd(&ssum[ty * 4 + r], ls[r]);
        atomicAdd(&ssq[ty * 4 + r], lq[r]);
    }
    __syncthreads();
    if (t < 64) {
        atomicAdd(&g_stats[256 + m0 + t], ssum[t]);
        atomicAdd(&g_stats[384 + m0 + t], ssq[t]);
    }
}

// ---------------- K8: BN2 apply + transpose to (B, C, N) ----------------
__global__ void __launch_bounds__(256) k_out(float* __restrict__ out) {
    __shared__ float tile[32][33];
    int b = blockIdx.z, c0 = blockIdx.y * 32, n0 = blockIdx.x * 32;
    int t = threadIdx.x, lx = t & 31, ly = t >> 5;
#pragma unroll
    for (int r = 0; r < 32; r += 8) {
        int n = n0 + ly + r;
        int pt = b * NNP + n;
        int c = c0 + lx;
        tile[ly + r][lx] = g_y2[(size_t)pt * CC + c] * g_sb2[c] + g_sb2[128 + c];
    }
    __syncthreads();
#pragma unroll
    for (int r = 0; r < 32; r += 8) {
        int c = c0 + ly + r;
        out[((size_t)b * CC + c) * NNP + n0 + lx] = tile[lx][ly + r];
    }
}

// ---------------- launch ----------------
extern "C" void kernel_launch(void* const* d_in, const int* in_sizes, int n_in,
                              void* d_out, int out_size) {
    const float* x  = (const float*)d_in[0];
    const float* Wq = (const float*)d_in[1];
    const float* Wk = (const float*)d_in[2];
    const float* Wv = (const float*)d_in[3];
    const float* W1 = (const float*)d_in[4];
    const float* W2 = (const float*)d_in[5];
    const float* g1 = (const float*)d_in[6];
    const float* b1 = (const float*)d_in[7];
    const float* g2 = (const float*)d_in[8];
    const float* b2 = (const float*)d_in[9];
    float* out = (float*)d_out;

    k_prep<<<64, 256>>>(x);
    k_dist<<<dim3(64, 64, 4), 256>>>(x);
    k_topk<<<16384, 256>>>();
    k_qkv<<<dim3(256, 6), 256>>>(x, Wq, Wk, Wv);
    k_attn<<<512, 256>>>(x);
    k_bnfin<<<1, 128>>>(g1, b1, 0);
    k_ffn1<<<dim3(256, 8), 256>>>(W1);
    k_ffn2<<<dim3(256, 2), 256>>>(W2);
    k_bnfin<<<1, 128>>>(g2, b2, 1);
    k_out<<<dim3(128, 4, 4), 256>>>(out);
}